// round 12
// baseline (speedup 1.0000x reference)
#include <cuda_runtime.h>
#include <cuda_fp16.h>
#include <math.h>
#include <stdint.h>

// Problem constants: B=2, L=2048, D=1024, N=16
#define M_ROWS 4096
#define K_DIM  1024
#define DN     16384

// ---------------------------------------------------------------------------
// Device scratch
// ---------------------------------------------------------------------------
__device__ __align__(256) __half g_u_h  [(size_t)M_ROWS * K_DIM];
__device__ __align__(256) __half g_Wdt_h[(size_t)1024  * K_DIM];
__device__ __align__(256) __half g_WB_h [(size_t)DN    * K_DIM];
__device__ __align__(256) __half g_WC_h [(size_t)DN    * K_DIM];
__device__ __align__(256) float  g_dt  [(size_t)M_ROWS * 1024];
__device__ __align__(256) __half g_Bt16[(size_t)M_ROWS * DN];
__device__ __align__(256) __half g_Ct16[(size_t)M_ROWS * DN];

// ---------------------------------------------------------------------------
// Helpers (family-portable PTX only)
// ---------------------------------------------------------------------------
__device__ __forceinline__ uint32_t smem_u32(const void* p) {
    uint32_t a;
    asm("{ .reg .u64 t; cvta.to.shared.u64 t, %1; cvt.u32.u64 %0, t; }"
        : "=r"(a) : "l"(p));
    return a;
}
__device__ __forceinline__ void cp16(uint32_t s, const void* g) {
    asm volatile("cp.async.cg.shared.global [%0], [%1], 16;" :: "r"(s), "l"(g));
}
#define CP_COMMIT() asm volatile("cp.async.commit_group;" ::: "memory")
#define CP_WAIT1()  asm volatile("cp.async.wait_group 1;"  ::: "memory")
#define CP_WAIT0()  asm volatile("cp.async.wait_group 0;"  ::: "memory")

__device__ __forceinline__ void ldsm4(uint32_t* r, uint32_t addr) {
    asm volatile("ldmatrix.sync.aligned.m8n8.x4.shared.b16 {%0,%1,%2,%3}, [%4];"
                 : "=r"(r[0]), "=r"(r[1]), "=r"(r[2]), "=r"(r[3]) : "r"(addr));
}
// fp32-accumulate fp16 MMA
__device__ __forceinline__ void mma16816(float* d, const uint32_t* a, const uint32_t* b) {
    asm volatile(
        "mma.sync.aligned.m16n8k16.row.col.f32.f16.f16.f32 "
        "{%0,%1,%2,%3}, {%4,%5,%6,%7}, {%8,%9}, {%0,%1,%2,%3};"
        : "+f"(d[0]), "+f"(d[1]), "+f"(d[2]), "+f"(d[3])
        : "r"(a[0]), "r"(a[1]), "r"(a[2]), "r"(a[3]), "r"(b[0]), "r"(b[1]));
}
// fp16-accumulate fp16 MMA (D=C=2x f16x2)
__device__ __forceinline__ void mma16816h(uint32_t* d, const uint32_t* a, const uint32_t* b) {
    asm volatile(
        "mma.sync.aligned.m16n8k16.row.col.f16.f16.f16.f16 "
        "{%0,%1}, {%2,%3,%4,%5}, {%6,%7}, {%0,%1};"
        : "+r"(d[0]), "+r"(d[1])
        : "r"(a[0]), "r"(a[1]), "r"(a[2]), "r"(a[3]), "r"(b[0]), "r"(b[1]));
}

// ---------------------------------------------------------------------------
// Merged split kernel: fp32 -> fp16, all sources, one launch.
// ---------------------------------------------------------------------------
#define U4    ((M_ROWS * K_DIM) / 4)
#define WDT4  ((1024 * K_DIM) / 4)
#define WBC4  ((DN * K_DIM) / 4)
#define T0    (U4)
#define T1    (T0 + WDT4)
#define T2    (T1 + WBC4)
#define T3    (T2 + WBC4)

__global__ __launch_bounds__(256)
void split_all_kernel(const float* __restrict__ u,
                      const float* __restrict__ W_dt,
                      const float* __restrict__ W_B,
                      const float* __restrict__ W_C)
{
    int i = blockIdx.x * 256 + threadIdx.x;
    if (i >= T3) return;

    const float* src;
    __half* dst;
    int idx;
    if (i < T0)      { src = u;    dst = g_u_h;   idx = i; }
    else if (i < T1) { src = W_dt; dst = g_Wdt_h; idx = i - T0; }
    else if (i < T2) { src = W_B;  dst = g_WB_h;  idx = i - T1; }
    else             { src = W_C;  dst = g_WC_h;  idx = i - T2; }

    float4 x = ((const float4*)src)[idx];
    __half h[4];
    h[0] = __float2half_rn(x.x); h[1] = __float2half_rn(x.y);
    h[2] = __float2half_rn(x.z); h[3] = __float2half_rn(x.w);
    *((uint2*)(dst + 4 * (size_t)idx)) = *(uint2*)h;
}

// ---------------------------------------------------------------------------
// Shared GEMM geometry
// ---------------------------------------------------------------------------
#define ROW_B     144                        // 128 data + 16 pad bytes
#define NSTAGE    3
#define A_BYTES   (128 * ROW_B)              // 18432
#define B_OFF     A_BYTES
#define STAGE_SZ  (A_BYTES + 256 * ROW_B)    // 55296
#define SMEM_GEMM (NSTAGE * STAGE_SZ)        // 165888

// ---------------------------------------------------------------------------
// fp32-acc GEMM: C (y<64, fp16 out) and dt (y>=64, fp32+softplus out).
// 512 threads, 16 warps (2m x 8n), warp tile 64x32, K-chunk 64, 3-stage.
// ---------------------------------------------------------------------------
__global__ __launch_bounds__(512, 1)
void gemm_cdt(const float* __restrict__ biasC,
              const float* __restrict__ biasDt,
              const float* __restrict__ dtBias2)
{
    extern __shared__ char smem[];
    const uint32_t sb = smem_u32(smem);
    const int tid = threadIdx.x;
    const int wid = tid >> 5;
    const int lane = tid & 31;
    const int mBase = blockIdx.x * 128;
    const int warp_m = (wid >> 3) * 64;
    const int warp_n = (wid & 7) * 32;

    const int byg = blockIdx.y;           // 0..67
    const bool isDt = byg >= 64;
    const __half* W = isDt ? g_Wdt_h : g_WC_h;
    const float* bias1 = isDt ? biasDt : biasC;
    const int nBase = isDt ? (byg - 64) * 256 : byg * 256;

    auto load_stage = [&](int s, int k0) {
        const uint32_t st = sb + (uint32_t)s * STAGE_SZ;
        #pragma unroll
        for (int i = 0; i < 2; i++) {
            int idx = i * 512 + tid;
            int row = idx >> 3, c = idx & 7;
            uint32_t so = (uint32_t)(row * ROW_B + c * 16);
            size_t go = (size_t)(mBase + row) * K_DIM + k0 + c * 8;
            cp16(st + so, g_u_h + go);
        }
        #pragma unroll
        for (int i = 0; i < 4; i++) {
            int idx = i * 512 + tid;
            int row = idx >> 3, c = idx & 7;
            uint32_t so = (uint32_t)(row * ROW_B + c * 16);
            size_t go = (size_t)(nBase + row) * K_DIM + k0 + c * 8;
            cp16(st + B_OFF + so, W + go);
        }
    };

    float acc[4][4][4];
    #pragma unroll
    for (int i = 0; i < 4; i++)
        #pragma unroll
        for (int j = 0; j < 4; j++)
            #pragma unroll
            for (int q = 0; q < 4; q++)
                acc[i][j][q] = 0.0f;

    const int aRow  = lane & 15;
    const int aHalf = lane >> 4;
    const int bJ    = lane & 7;
    const int bG    = lane >> 3;
    const int bRow  = (bG >> 1) * 8 + bJ;
    const int bHalf = bG & 1;

    load_stage(0, 0);   CP_COMMIT();
    load_stage(1, 64);  CP_COMMIT();

    const int NCHUNK = K_DIM / 64;        // 16
    for (int c = 0; c < NCHUNK; c++) {
        CP_WAIT1();
        __syncthreads();

        if (c + 2 < NCHUNK) load_stage((c + 2) % NSTAGE, (c + 2) * 64);
        CP_COMMIT();

        const uint32_t st = sb + (uint32_t)(c % NSTAGE) * STAGE_SZ;
        #pragma unroll
        for (int ks = 0; ks < 4; ks++) {
            const uint32_t kOff = ks * 32;
            uint32_t ah[4][4], bh[4][2];
            #pragma unroll
            for (int i = 0; i < 4; i++) {
                uint32_t ao = (uint32_t)((warp_m + i * 16 + aRow) * ROW_B)
                              + kOff + aHalf * 16;
                ldsm4(ah[i], st + ao);
            }
            #pragma unroll
            for (int j = 0; j < 2; j++) {
                uint32_t bo = (uint32_t)((warp_n + j * 16 + bRow) * ROW_B)
                              + kOff + bHalf * 16;
                uint32_t rh[4];
                ldsm4(rh, st + B_OFF + bo);
                bh[2*j][0] = rh[0]; bh[2*j][1] = rh[1];
                bh[2*j+1][0] = rh[2]; bh[2*j+1][1] = rh[3];
            }
            #pragma unroll
            for (int i = 0; i < 4; i++)
                #pragma unroll
                for (int j = 0; j < 4; j++)
                    mma16816(acc[i][j], ah[i], bh[j]);
        }
    }
    CP_WAIT0();

    const int r0 = (lane >> 2);
    const int c0 = (lane & 3) * 2;
    #pragma unroll
    for (int i = 0; i < 4; i++) {
        const int gr0 = mBase + warp_m + i * 16 + r0;
        #pragma unroll
        for (int j = 0; j < 4; j++) {
            const int gc = nBase + warp_n + j * 8 + c0;
            float v0 = acc[i][j][0] + bias1[gc];
            float v1 = acc[i][j][1] + bias1[gc + 1];
            float v2 = acc[i][j][2] + bias1[gc];
            float v3 = acc[i][j][3] + bias1[gc + 1];
            if (isDt) {
                v0 += dtBias2[gc];     v1 += dtBias2[gc + 1];
                v2 += dtBias2[gc];     v3 += dtBias2[gc + 1];
                v0 = fmaxf(v0, 0.0f) + log1pf(__expf(-fabsf(v0)));
                v1 = fmaxf(v1, 0.0f) + log1pf(__expf(-fabsf(v1)));
                v2 = fmaxf(v2, 0.0f) + log1pf(__expf(-fabsf(v2)));
                v3 = fmaxf(v3, 0.0f) + log1pf(__expf(-fabsf(v3)));
                *(float2*)(g_dt + (size_t)gr0       * 1024 + gc) = make_float2(v0, v1);
                *(float2*)(g_dt + (size_t)(gr0 + 8) * 1024 + gc) = make_float2(v2, v3);
            } else {
                *(__half2*)(g_Ct16 + (size_t)gr0       * DN + gc) = __floats2half2_rn(v0, v1);
                *(__half2*)(g_Ct16 + (size_t)(gr0 + 8) * DN + gc) = __floats2half2_rn(v2, v3);
            }
        }
    }
}

// ---------------------------------------------------------------------------
// EXPERIMENT: fp16-accumulate GEMM for B (y in [0,64), fp16 out).
// Same geometry; accumulates in fp16 (mma f16.f16.f16.f16), drains to fp32
// every 2 k-steps (K=32 per fp16 group).
// ---------------------------------------------------------------------------
__global__ __launch_bounds__(512, 1)
void gemm_b_h(const float* __restrict__ biasB)
{
    extern __shared__ char smem[];
    const uint32_t sb = smem_u32(smem);
    const int tid = threadIdx.x;
    const int wid = tid >> 5;
    const int lane = tid & 31;
    const int mBase = blockIdx.x * 128;
    const int warp_m = (wid >> 3) * 64;
    const int warp_n = (wid & 7) * 32;
    const int nBase = blockIdx.y * 256;

    auto load_stage = [&](int s, int k0) {
        const uint32_t st = sb + (uint32_t)s * STAGE_SZ;
        #pragma unroll
        for (int i = 0; i < 2; i++) {
            int idx = i * 512 + tid;
            int row = idx >> 3, c = idx & 7;
            uint32_t so = (uint32_t)(row * ROW_B + c * 16);
            size_t go = (size_t)(mBase + row) * K_DIM + k0 + c * 8;
            cp16(st + so, g_u_h + go);
        }
        #pragma unroll
        for (int i = 0; i < 4; i++) {
            int idx = i * 512 + tid;
            int row = idx >> 3, c = idx & 7;
            uint32_t so = (uint32_t)(row * ROW_B + c * 16);
            size_t go = (size_t)(nBase + row) * K_DIM + k0 + c * 8;
            cp16(st + B_OFF + so, g_WB_h + go);
        }
    };

    float acc[4][4][4];
    #pragma unroll
    for (int i = 0; i < 4; i++)
        #pragma unroll
        for (int j = 0; j < 4; j++)
            #pragma unroll
            for (int q = 0; q < 4; q++)
                acc[i][j][q] = 0.0f;

    uint32_t hacc[4][4][2];
    #pragma unroll
    for (int i = 0; i < 4; i++)
        #pragma unroll
        for (int j = 0; j < 4; j++)
            hacc[i][j][0] = hacc[i][j][1] = 0u;

    const int aRow  = lane & 15;
    const int aHalf = lane >> 4;
    const int bJ    = lane & 7;
    const int bG    = lane >> 3;
    const int bRow  = (bG >> 1) * 8 + bJ;
    const int bHalf = bG & 1;

    load_stage(0, 0);   CP_COMMIT();
    load_stage(1, 64);  CP_COMMIT();

    const int NCHUNK = K_DIM / 64;        // 16
    for (int c = 0; c < NCHUNK; c++) {
        CP_WAIT1();
        __syncthreads();

        if (c + 2 < NCHUNK) load_stage((c + 2) % NSTAGE, (c + 2) * 64);
        CP_COMMIT();

        const uint32_t st = sb + (uint32_t)(c % NSTAGE) * STAGE_SZ;
        #pragma unroll
        for (int ks = 0; ks < 4; ks++) {
            const uint32_t kOff = ks * 32;
            uint32_t ah[4][4], bh[4][2];
            #pragma unroll
            for (int i = 0; i < 4; i++) {
                uint32_t ao = (uint32_t)((warp_m + i * 16 + aRow) * ROW_B)
                              + kOff + aHalf * 16;
                ldsm4(ah[i], st + ao);
            }
            #pragma unroll
            for (int j = 0; j < 2; j++) {
                uint32_t bo = (uint32_t)((warp_n + j * 16 + bRow) * ROW_B)
                              + kOff + bHalf * 16;
                uint32_t rh[4];
                ldsm4(rh, st + B_OFF + bo);
                bh[2*j][0] = rh[0]; bh[2*j][1] = rh[1];
                bh[2*j+1][0] = rh[2]; bh[2*j+1][1] = rh[3];
            }
            #pragma unroll
            for (int i = 0; i < 4; i++)
                #pragma unroll
                for (int j = 0; j < 4; j++)
                    mma16816h(hacc[i][j], ah[i], bh[j]);

            if (ks & 1) {   // drain every 2 k-steps (K=32 per fp16 group)
                #pragma unroll
                for (int i = 0; i < 4; i++)
                    #pragma unroll
                    for (int j = 0; j < 4; j++) {
                        float2 f0 = __half22float2(*(__half2*)&hacc[i][j][0]);
                        float2 f1 = __half22float2(*(__half2*)&hacc[i][j][1]);
                        acc[i][j][0] += f0.x; acc[i][j][1] += f0.y;
                        acc[i][j][2] += f1.x; acc[i][j][3] += f1.y;
                        hacc[i][j][0] = 0u;   hacc[i][j][1] = 0u;
                    }
            }
        }
    }
    CP_WAIT0();

    const int r0 = (lane >> 2);
    const int c0 = (lane & 3) * 2;
    #pragma unroll
    for (int i = 0; i < 4; i++) {
        const int gr0 = mBase + warp_m + i * 16 + r0;
        #pragma unroll
        for (int j = 0; j < 4; j++) {
            const int gc = nBase + warp_n + j * 8 + c0;
            float v0 = acc[i][j][0] + biasB[gc];
            float v1 = acc[i][j][1] + biasB[gc + 1];
            float v2 = acc[i][j][2] + biasB[gc];
            float v3 = acc[i][j][3] + biasB[gc + 1];
            *(__half2*)(g_Bt16 + (size_t)gr0       * DN + gc) = __floats2half2_rn(v0, v1);
            *(__half2*)(g_Bt16 + (size_t)(gr0 + 8) * DN + gc) = __floats2half2_rn(v2, v3);
        }
    }
}

// ---------------------------------------------------------------------------
// Scan: one thread per (b, d, n). Block = 8 d x 16 n = 128 thr. Grid = 256.
// ---------------------------------------------------------------------------
__global__ __launch_bounds__(128)
void scan_kernel(const float* __restrict__ u,
                 const float* __restrict__ logA,
                 const float* __restrict__ Dskip,
                 float* __restrict__ y)
{
    const int tid  = threadIdx.x;
    const int n    = tid & 15;
    const int dl   = tid >> 4;
    const int blk  = blockIdx.x;
    const int b    = blk >> 7;
    const int dblk = blk & 127;
    const int d    = dblk * 8 + dl;

    const float Aval = -__expf(logA[d * 16 + n]);
    const float invA = 1.0f / Aval;
    const float dsk  = Dskip[d];

    const float*  uB  = u      + (size_t)b * 2048 * 1024;
    const float*  dtB = g_dt   + (size_t)b * 2048 * 1024;
    const __half* BtB = g_Bt16 + (size_t)b * 2048 * DN;
    const __half* CtB = g_Ct16 + (size_t)b * 2048 * DN;
    float*        yB  = y      + (size_t)b * 2048 * 1024;

    const int off = dblk * 128 + tid;

    float h = 0.0f;
    #pragma unroll 2
    for (int t = 0; t < 2048; ++t) {
        const float uv  = uB [t * 1024 + d];
        const float dtv = dtB[t * 1024 + d];
        const float Btv = __half2float(BtB[(size_t)t * DN + off]);
        const float Ctv = __half2float(CtB[(size_t)t * DN + off]);

        const float a = __expf(dtv * Aval);
        const float x = (a - 1.0f) * invA * Btv * uv;
        h = fmaf(a, h, x);

        float p = Ctv * h;
        p += __shfl_down_sync(0xffffffffu, p, 8, 16);
        p += __shfl_down_sync(0xffffffffu, p, 4, 16);
        p += __shfl_down_sync(0xffffffffu, p, 2, 16);
        p += __shfl_down_sync(0xffffffffu, p, 1, 16);

        if (n == 0)
            yB[t * 1024 + d] = p + dsk * uv;
    }
}

// ---------------------------------------------------------------------------
extern "C" void kernel_launch(void* const* d_in, const int* in_sizes, int n_in,
                              void* d_out, int out_size)
{
    const float* u       = (const float*)d_in[0];
    const float* log_A   = (const float*)d_in[1];
    const float* D_skip  = (const float*)d_in[2];
    const float* dt_bias = (const float*)d_in[3];
    const float* W_dt    = (const float*)d_in[4];
    const float* b_dt    = (const float*)d_in[5];
    const float* W_B     = (const float*)d_in[6];
    const float* b_B     = (const float*)d_in[7];
    const float* W_C     = (const float*)d_in[8];
    const float* b_C     = (const float*)d_in[9];
    float* y = (float*)d_out;

    cudaFuncSetAttribute(gemm_cdt, cudaFuncAttributeMaxDynamicSharedMemorySize, SMEM_GEMM);
    cudaFuncSetAttribute(gemm_b_h, cudaFuncAttributeMaxDynamicSharedMemorySize, SMEM_GEMM);

    // merged fp32 -> fp16 split
    split_all_kernel<<<(T3 + 255) / 256, 256>>>(u, W_dt, W_B, W_C);

    // EXPERIMENT: B via fp16-accumulate HMMA (drain every K=32)
    gemm_b_h<<<dim3(32, 64), 512, SMEM_GEMM>>>(b_B);
    // C + dt via known-good fp32-accumulate HMMA
    gemm_cdt<<<dim3(32, 68), 512, SMEM_GEMM>>>(b_C, b_dt, dt_bias);

    // fused discretization + recurrent scan + skip
    scan_kernel<<<256, 128>>>(u, log_A, D_skip, y);
}